// round 7
// baseline (speedup 1.0000x reference)
#include <cuda_runtime.h>

// Upscale2d: 2x zero-insert upsample + 4x4 binomial FIR == separable 2-tap
// polyphase: even (a + 3b)/4, odd (3b + c)/4 per axis.
// x: [8,64,256,256] f32 -> y: [8,64,512,512] f32, zero-padded borders.
//
// Two input rows processed per iteration (independent load/shuffle/store
// chains -> 2x per-warp MLP), software-pipelined one row-pair ahead.
// Horizontal neighbors via warp shuffle; lanes 0/31 predicated edge loads.
// float4 streaming stores (512B contiguous per warp per output row).

#define IN_H 256
#define IN_W 256
#define OUT_W 512
#define RPT 8   // input rows per thread (even)

__global__ __launch_bounds__(256, 7) void upscale2d_kernel(
    const float* __restrict__ x, float* __restrict__ y)
{
    const int t    = threadIdx.x & 127;        // owns input cols [2t, 2t+1]
    const int sub  = threadIdx.x >> 7;         // 0/1: row-group within block
    const int g    = blockIdx.x * 2 + sub;     // row group
    const int p    = blockIdx.y;               // plane (N*C)
    const int lane = threadIdx.x & 31;

    const int c0 = 2 * t;
    const float* xp = x + (size_t)p * IN_H * IN_W;
    float*       yp = y + (size_t)p * OUT_W * OUT_W;
    const int r0 = g * RPT;

    const bool edgeL = (lane == 0)  && (c0 >= 1);
    const bool edgeR = (lane == 31) && (c0 + 2 < IN_W);

    // raw row load (zero outside [0, IN_H)); e = cross-warp edge element
    auto loadraw = [&](int r, float& e) -> float2 {
        e = 0.f;
        if (r < 0 || r >= IN_H) return make_float2(0.f, 0.f);
        const float* row = xp + (size_t)r * IN_W;
        if (edgeL) e = __ldg(row + c0 - 1);
        if (edgeR) e = __ldg(row + c0 + 2);
        return *(const float2*)(row + c0);
    };

    // horizontal pre-combines: H = even phase, O = odd phase (x2 columns)
    auto comb = [&](float2 c, float e,
                    float& H0, float& O0, float& H1, float& O1) {
        float l  = __shfl_up_sync(0xffffffffu, c.y, 1);   // col c0-1
        float rr = __shfl_down_sync(0xffffffffu, c.x, 1); // col c0+2
        if (lane == 0)  l  = e;
        if (lane == 31) rr = e;
        H0 = l   + 3.f * c.x;  O0 = 3.f * c.x + c.y;
        H1 = c.x + 3.f * c.y;  O1 = 3.f * c.y + rr;
    };

    // prologue: rows r0-1 (combined into P), r0, r0+1 (raw, pipelined)
    float eP, eA, eB;
    float2 rP = loadraw(r0 - 1, eP);
    float2 rA = loadraw(r0,     eA);
    float2 rB = loadraw(r0 + 1, eB);

    float PH0, PO0, PH1, PO1;
    comb(rP, eP, PH0, PO0, PH1, PO1);

    #pragma unroll
    for (int i = 0; i < RPT; i += 2) {
        const int k = r0 + i;

        // prefetch next row pair (or the epilogue row) FIRST
        float eA2 = 0.f, eB2 = 0.f;
        float2 rA2 = make_float2(0.f, 0.f), rB2 = make_float2(0.f, 0.f);
        if (i + 2 < RPT) {
            rA2 = loadraw(k + 2, eA2);
            rB2 = loadraw(k + 3, eB2);
        } else {
            rA2 = loadraw(r0 + RPT, eA2);   // epilogue row
        }

        // combine current pair (two independent chains)
        float AH0, AO0, AH1, AO1, BH0, BO0, BH1, BO1;
        comb(rA, eA, AH0, AO0, AH1, AO1);
        comb(rB, eB, BH0, BO0, BH1, BO1);

        float* obase = yp + (size_t)(2 * k) * OUT_W + 2 * c0;

        // out[2k-1] = (3*P + A)/16   (first row belongs to prev CTA at i==0)
        if (i > 0) {
            float4 v;
            v.x = (3.f * PH0 + AH0) * 0.0625f;
            v.y = (3.f * PO0 + AO0) * 0.0625f;
            v.z = (3.f * PH1 + AH1) * 0.0625f;
            v.w = (3.f * PO1 + AO1) * 0.0625f;
            __stcs((float4*)(obase - OUT_W), v);
        }
        // out[2k] = (P + 3*A)/16
        {
            float4 v;
            v.x = (PH0 + 3.f * AH0) * 0.0625f;
            v.y = (PO0 + 3.f * AO0) * 0.0625f;
            v.z = (PH1 + 3.f * AH1) * 0.0625f;
            v.w = (PO1 + 3.f * AO1) * 0.0625f;
            __stcs((float4*)(obase), v);
        }
        // out[2k+1] = (3*A + B)/16
        {
            float4 v;
            v.x = (3.f * AH0 + BH0) * 0.0625f;
            v.y = (3.f * AO0 + BO0) * 0.0625f;
            v.z = (3.f * AH1 + BH1) * 0.0625f;
            v.w = (3.f * AO1 + BO1) * 0.0625f;
            __stcs((float4*)(obase + OUT_W), v);
        }
        // out[2k+2] = (A + 3*B)/16
        {
            float4 v;
            v.x = (AH0 + 3.f * BH0) * 0.0625f;
            v.y = (AO0 + 3.f * BO0) * 0.0625f;
            v.z = (AH1 + 3.f * BH1) * 0.0625f;
            v.w = (AO1 + 3.f * BO1) * 0.0625f;
            __stcs((float4*)(obase + 2 * OUT_W), v);
        }

        // roll: P <- B, (A,B) <- prefetched
        PH0 = BH0; PO0 = BO0; PH1 = BH1; PO1 = BO1;
        rA = rA2; eA = eA2; rB = rB2; eB = eB2;
    }

    // epilogue: C = comb(row r0+RPT) (already in rA); out[2(r0+RPT)-1]
    {
        float CH0, CO0, CH1, CO1;
        comb(rA, eA, CH0, CO0, CH1, CO1);
        float4 v;
        v.x = (3.f * PH0 + CH0) * 0.0625f;
        v.y = (3.f * PO0 + CO0) * 0.0625f;
        v.z = (3.f * PH1 + CH1) * 0.0625f;
        v.w = (3.f * PO1 + CO1) * 0.0625f;
        __stcs((float4*)(yp + (size_t)(2 * (r0 + RPT) - 1) * OUT_W + 2 * c0), v);
    }
}

extern "C" void kernel_launch(void* const* d_in, const int* in_sizes, int n_in,
                              void* d_out, int out_size)
{
    const float* x = (const float*)d_in[0];
    float* y = (float*)d_out;
    int planes = in_sizes[0] / (IN_H * IN_W);            // 512
    dim3 grid(IN_H / (RPT * 2), planes);                 // (16, 512)
    upscale2d_kernel<<<grid, 256>>>(x, y);
}

// round 8
// speedup vs baseline: 1.2338x; 1.2338x over previous
#include <cuda_runtime.h>

// Upscale2d: 2x zero-insert upsample + 4x4 binomial FIR == separable 2-tap
// polyphase: even (a + 3b)/4, odd (3b + c)/4 per axis.
// x: [8,64,256,256] f32 -> y: [8,64,512,512] f32, zero-padded borders.
//
// Each thread owns 2 input columns (float2) x RPT=8 input rows (rolling
// vertical window). Horizontal neighbors via warp shuffle (lanes 0/31 do a
// predicated edge load). Row loads software-pipelined at DISTANCE 2: two
// independent LDGs in flight per thread at all times. float4 streaming
// stores (512B contiguous per warp per output row). No launch-bounds clamp
// (R6 lesson: forcing regs causes spills -> L1 blowup).

#define IN_H 256
#define IN_W 256
#define OUT_W 512
#define RPT 8   // input rows per thread

__global__ __launch_bounds__(256) void upscale2d_kernel(
    const float* __restrict__ x, float* __restrict__ y)
{
    const int t    = threadIdx.x & 127;        // owns input cols [2t, 2t+1]
    const int sub  = threadIdx.x >> 7;         // 0/1: row-group within block
    const int g    = blockIdx.x * 2 + sub;     // row group
    const int p    = blockIdx.y;               // plane (N*C)
    const int lane = threadIdx.x & 31;

    const int c0 = 2 * t;
    const float* xp = x + (size_t)p * IN_H * IN_W;
    float*       yp = y + (size_t)p * OUT_W * OUT_W;
    const int r0 = g * RPT;

    const bool edgeL = (lane == 0)  && (c0 >= 1);
    const bool edgeR = (lane == 31) && (c0 + 2 < IN_W);

    // raw row load (zero outside [0, IN_H)); e = cross-warp edge element
    auto loadraw = [&](int r, float& e) -> float2 {
        e = 0.f;
        if (r < 0 || r >= IN_H) return make_float2(0.f, 0.f);
        const float* row = xp + (size_t)r * IN_W;
        if (edgeL) e = __ldg(row + c0 - 1);
        if (edgeR) e = __ldg(row + c0 + 2);
        return *(const float2*)(row + c0);
    };

    // horizontal pre-combines: H = even phase, O = odd phase (2 columns)
    auto comb = [&](float2 c, float e,
                    float& H0, float& O0, float& H1, float& O1) {
        float l  = __shfl_up_sync(0xffffffffu, c.y, 1);   // col c0-1
        float rr = __shfl_down_sync(0xffffffffu, c.x, 1); // col c0+2
        if (lane == 0)  l  = e;
        if (lane == 31) rr = e;
        H0 = l   + 3.f * c.x;  O0 = 3.f * c.x + c.y;
        H1 = c.x + 3.f * c.y;  O1 = 3.f * c.y + rr;
    };

    // prologue: 3 loads issued back-to-back (r0-1, r0, r0+1)
    float ePr, eA, eB;
    float2 rPr = loadraw(r0 - 1, ePr);
    float2 rA  = loadraw(r0,     eA);   // consumed at i=0
    float2 rB  = loadraw(r0 + 1, eB);   // consumed at i=1

    float pH0, pO0, pH1, pO1;
    comb(rPr, ePr, pH0, pO0, pH1, pO1);

    #pragma unroll
    for (int i = 0; i <= RPT; i++) {
        const int r = r0 + i;

        // prefetch row r+2 FIRST (keeps 2 LDGs in flight)
        float eF = 0.f;
        float2 rF = make_float2(0.f, 0.f);
        if (i + 2 <= RPT) rF = loadraw(r + 2, eF);

        // combine current row (loaded 2 iterations ago)
        float cH0, cO0, cH1, cO1;
        comb(rA, eA, cH0, cO0, cH1, cO1);

        // output row 2r-1: vertical odd phase (3*prev + cur) * 1/16
        if (i > 0) {
            float4 v;
            v.x = (3.f * pH0 + cH0) * 0.0625f;
            v.y = (3.f * pO0 + cO0) * 0.0625f;
            v.z = (3.f * pH1 + cH1) * 0.0625f;
            v.w = (3.f * pO1 + cO1) * 0.0625f;
            __stcs((float4*)(yp + (size_t)(2 * r - 1) * OUT_W + 2 * c0), v);
        }
        // output row 2r: vertical even phase (prev + 3*cur) * 1/16
        if (i < RPT) {
            float4 v;
            v.x = (pH0 + 3.f * cH0) * 0.0625f;
            v.y = (pO0 + 3.f * cO0) * 0.0625f;
            v.z = (pH1 + 3.f * cH1) * 0.0625f;
            v.w = (pO1 + 3.f * cO1) * 0.0625f;
            __stcs((float4*)(yp + (size_t)(2 * r) * OUT_W + 2 * c0), v);
        }

        pH0 = cH0; pO0 = cO0; pH1 = cH1; pO1 = cO1;
        rA = rB; eA = eB;        // shift the 2-slot buffer
        rB = rF; eB = eF;
    }
}

extern "C" void kernel_launch(void* const* d_in, const int* in_sizes, int n_in,
                              void* d_out, int out_size)
{
    const float* x = (const float*)d_in[0];
    float* y = (float*)d_out;
    int planes = in_sizes[0] / (IN_H * IN_W);            // 512
    dim3 grid(IN_H / (RPT * 2), planes);                 // (16, 512)
    upscale2d_kernel<<<grid, 256>>>(x, y);
}